// round 4
// baseline (speedup 1.0000x reference)
#include <cuda_runtime.h>

// Problem constants
#define NN   4096
#define EE   32768
#define NEFD 128
#define HIDD 128
#define M0   64
#define M1   16
#define DIMX 112          // M0 + 3*M1
#define WA   4096         // M0*M0
#define WB   1024         // M0*M1
#define WC   256          // M1*M1
#define WD   1024         // M1*M0
#define WNUM 6400

// Tile / smem layout constants
#define TM   64           // edges per block
#define HS   132          // h row stride (pad 128 -> 132, conflict-free)
#define SS   65           // s row stride
#define VS   51           // v row stride (48 used)
#define PS   17           // p row stride (16 used)

#define N0C  0.11180339887498948f   // sqrt(1/80)
#define N1C  0.19364916731037085f   // sqrt(3/80)
#define I3C  0.57735026918962576f   // 1/sqrt(3)

// Scratch (device globals -- no allocation allowed)
__device__ float g_W2T[WNUM * HIDD];   // W2 transposed: [c][k]
__device__ float g_sums[NN * DIMX];
__device__ float g_cnt[NN];

__global__ void zero_kernel() {
    int i = blockIdx.x * blockDim.x + threadIdx.x;
    if (i < NN * DIMX) g_sums[i] = 0.0f;
    if (i < NN)        g_cnt[i]  = 0.0f;
}

// W2 is [HID][WNUM] row-major; produce W2T [WNUM][HID] so K is contiguous.
__global__ void transpose_w2(const float* __restrict__ W2) {
    int idx = blockIdx.x * blockDim.x + threadIdx.x;   // idx = k*WNUM + c
    if (idx >= WNUM * HIDD) return;
    int c = idx % WNUM;
    int k = idx / WNUM;
    g_W2T[c * HIDD + k] = W2[idx];
}

// 4 simultaneous dots of length 128: w[j] = b2[c0+j] + <h, W2T[c0+j]>
__device__ __forceinline__ float4 dot4(const float4* __restrict__ h4, int c0,
                                       const float* __restrict__ b2) {
    const float4* w0 = (const float4*)(g_W2T + c0 * HIDD);
    const float4* w1 = w0 + 32;
    const float4* w2 = w0 + 64;
    const float4* w3 = w0 + 96;
    float4 d0 = make_float4(0.f, 0.f, 0.f, 0.f);
    float4 d1 = d0, d2 = d0, d3 = d0;
#pragma unroll 8
    for (int k = 0; k < 32; ++k) {
        float4 hv = h4[k];
        float4 a = w0[k];
        float4 b = w1[k];
        float4 c = w2[k];
        float4 d = w3[k];
        d0.x = fmaf(hv.x, a.x, d0.x); d0.y = fmaf(hv.y, a.y, d0.y);
        d0.z = fmaf(hv.z, a.z, d0.z); d0.w = fmaf(hv.w, a.w, d0.w);
        d1.x = fmaf(hv.x, b.x, d1.x); d1.y = fmaf(hv.y, b.y, d1.y);
        d1.z = fmaf(hv.z, b.z, d1.z); d1.w = fmaf(hv.w, b.w, d1.w);
        d2.x = fmaf(hv.x, c.x, d2.x); d2.y = fmaf(hv.y, c.y, d2.y);
        d2.z = fmaf(hv.z, c.z, d2.z); d2.w = fmaf(hv.w, c.w, d2.w);
        d3.x = fmaf(hv.x, d.x, d3.x); d3.y = fmaf(hv.y, d.y, d3.y);
        d3.z = fmaf(hv.z, d.z, d3.z); d3.w = fmaf(hv.w, d.w, d3.w);
    }
    float4 r;
    r.x = (d0.x + d0.y) + (d0.z + d0.w) + b2[c0 + 0];
    r.y = (d1.x + d1.y) + (d1.z + d1.w) + b2[c0 + 1];
    r.z = (d2.x + d2.y) + (d2.z + d2.w) + b2[c0 + 2];
    r.w = (d3.x + d3.y) + (d3.z + d3.w) + b2[c0 + 3];
    return r;
}

// Fused: h = relu(ea@W1+b1); per-edge w = h@W2+b2 consumed on the fly into
// the tensor-product contraction; scatter-add by src.
__global__ __launch_bounds__(256, 2)
void tp_main(const float* __restrict__ node_attr,
             const int*   __restrict__ edge_index,
             const float* __restrict__ edge_attr,
             const float* __restrict__ edge_sh,
             const float* __restrict__ W1,
             const float* __restrict__ b1,
             const float* __restrict__ b2)
{
    extern __shared__ float sm[];
    float* h_sm  = sm;                       // TM*HS  = 8448 floats
    float* un    = sm + TM * HS;             // union: ea tile, then s/v/p (8512)
    float* sh0_s = un + 8512;                // TM
    float* sh1_s = sh0_s + TM;               // TM*4

    const int tid = threadIdx.x;
    const int e0  = blockIdx.x * TM;

    // ---- phase 1: edge_sh + edge counts ----
    if (tid < TM) {
        int e = e0 + tid;
        float4 shv = *(const float4*)(edge_sh + e * 4);
        sh0_s[tid] = shv.x;
        sh1_s[tid * 4 + 0] = shv.y;
        sh1_s[tid * 4 + 1] = shv.z;
        sh1_s[tid * 4 + 2] = shv.w;
        atomicAdd(&g_cnt[edge_index[e]], 1.0f);   // src = row 0
    }

    // ---- phase 2: load edge_attr tile (into union region) ----
    float* ea = un;
    {
        const float4* src4 = (const float4*)(edge_attr + (size_t)e0 * NEFD);
        for (int i = tid; i < TM * (NEFD / 4); i += 256) {
            int e  = i >> 5;       // /32 float4 per row
            int j4 = i & 31;
            float4 v = src4[i];
            *(float4*)&ea[e * HS + j4 * 4] = v;
        }
    }
    __syncthreads();

    // ---- phase 3: h = relu(ea @ W1 + b1) into h_sm ----
    {
        const int cg = tid & 15;       // col group: cols 8*cg .. 8*cg+7
        const int eg = tid >> 4;       // edge group: edges 4*eg .. 4*eg+3
        const int c0 = cg * 8;
        float acc[4][8];
#pragma unroll
        for (int q = 0; q < 4; ++q)
#pragma unroll
            for (int m = 0; m < 8; ++m) acc[q][m] = 0.f;
#pragma unroll 4
        for (int j = 0; j < NEFD; ++j) {
            float4 wlo = *(const float4*)(W1 + j * HIDD + c0);
            float4 whi = *(const float4*)(W1 + j * HIDD + c0 + 4);
            float wv[8] = {wlo.x, wlo.y, wlo.z, wlo.w, whi.x, whi.y, whi.z, whi.w};
#pragma unroll
            for (int q = 0; q < 4; ++q) {
                float a = ea[(4 * eg + q) * HS + j];
#pragma unroll
                for (int m = 0; m < 8; ++m) acc[q][m] = fmaf(a, wv[m], acc[q][m]);
            }
        }
#pragma unroll
        for (int q = 0; q < 4; ++q)
#pragma unroll
            for (int m = 0; m < 8; ++m)
                h_sm[(4 * eg + q) * HS + c0 + m] = fmaxf(acc[q][m] + b1[c0 + m], 0.f);
    }
    __syncthreads();

    // ---- phase 4: gather node_attr[dst] -> s/v (overwrites ea) ----
    float* s_sm = un;                    // [TM][SS]
    float* v_sm = un + TM * SS;          // [TM][VS]
    float* p_sm = un + TM * SS + TM * VS;// [TM][PS]
    const int el = tid >> 2;
    const int r  = tid & 3;
    {
        int dstn = edge_index[EE + e0 + el];       // dst = row 1
        const float4* nb = (const float4*)(node_attr + (size_t)dstn * DIMX);
#pragma unroll
        for (int t = 0; t < 7; ++t) {
            int f4  = r * 7 + t;                    // 0..27
            float4 v = nb[f4];
            int col = f4 * 4;
            if (col < M0) {
                s_sm[el * SS + col + 0] = v.x;
                s_sm[el * SS + col + 1] = v.y;
                s_sm[el * SS + col + 2] = v.z;
                s_sm[el * SS + col + 3] = v.w;
            } else {
                int q = col - M0;
                v_sm[el * VS + q + 0] = v.x;
                v_sm[el * VS + q + 1] = v.y;
                v_sm[el * VS + q + 2] = v.z;
                v_sm[el * VS + q + 3] = v.w;
            }
        }
    }
    __syncthreads();

    // ---- phase 5: p[u] = (1/sqrt3) * (v[u] . sh1) ----
    {
        float s1x = sh1_s[el * 4 + 0], s1y = sh1_s[el * 4 + 1], s1z = sh1_s[el * 4 + 2];
#pragma unroll
        for (int q = 0; q < 4; ++q) {
            int u = r * 4 + q;
            float pv = v_sm[el * VS + u * 3 + 0] * s1x
                     + v_sm[el * VS + u * 3 + 1] * s1y
                     + v_sm[el * VS + u * 3 + 2] * s1z;
            p_sm[el * PS + u] = I3C * pv;
        }
    }
    __syncthreads();

    // ---- phase 6: fused GEMM + contraction ----
    {
        const float4* h4 = (const float4*)(h_sm + el * HS);
        const float sh0v = sh0_s[el];
        float acc0[16], accB[4], accC[12];
#pragma unroll
        for (int m = 0; m < 16; ++m) acc0[m] = 0.f;
#pragma unroll
        for (int m = 0; m < 4; ++m)  accB[m] = 0.f;
#pragma unroll
        for (int m = 0; m < 12; ++m) accC[m] = 0.f;

        // Region A: c = u*64 + w',  acc0[w'] += (sh0*s[u]) * w[c]
        for (int u = 0; u < M0; ++u) {
            float lf = sh0v * s_sm[el * SS + u];
            int cb = u * 64 + r * 16;
#pragma unroll
            for (int g = 0; g < 4; ++g) {
                float4 w = dot4(h4, cb + 4 * g, b2);
                acc0[4 * g + 0] = fmaf(lf, w.x, acc0[4 * g + 0]);
                acc0[4 * g + 1] = fmaf(lf, w.y, acc0[4 * g + 1]);
                acc0[4 * g + 2] = fmaf(lf, w.z, acc0[4 * g + 2]);
                acc0[4 * g + 3] = fmaf(lf, w.w, acc0[4 * g + 3]);
            }
        }
        // Region D: c = 5376 + u*64 + w',  acc0[w'] += p[u] * w[c]  (p has 1/sqrt3)
        for (int u = 0; u < M1; ++u) {
            float lf = p_sm[el * PS + u];
            int cb = (WA + WB + WC) + u * 64 + r * 16;
#pragma unroll
            for (int g = 0; g < 4; ++g) {
                float4 w = dot4(h4, cb + 4 * g, b2);
                acc0[4 * g + 0] = fmaf(lf, w.x, acc0[4 * g + 0]);
                acc0[4 * g + 1] = fmaf(lf, w.y, acc0[4 * g + 1]);
                acc0[4 * g + 2] = fmaf(lf, w.z, acc0[4 * g + 2]);
                acc0[4 * g + 3] = fmaf(lf, w.w, acc0[4 * g + 3]);
            }
        }
        // Region B: c = 4096 + u*16 + w',  accB[w'] += s[u] * w[c]
        for (int u = 0; u < M0; ++u) {
            float lf = s_sm[el * SS + u];
            float4 w = dot4(h4, WA + u * 16 + r * 4, b2);
            accB[0] = fmaf(lf, w.x, accB[0]);
            accB[1] = fmaf(lf, w.y, accB[1]);
            accB[2] = fmaf(lf, w.z, accB[2]);
            accB[3] = fmaf(lf, w.w, accB[3]);
        }
        // Region C: c = 5120 + u*16 + w',  accC[w',i] += v[u,i] * w[c]
        for (int u = 0; u < M1; ++u) {
            float v0 = v_sm[el * VS + u * 3 + 0];
            float v1 = v_sm[el * VS + u * 3 + 1];
            float v2 = v_sm[el * VS + u * 3 + 2];
            float4 w = dot4(h4, WA + WB + u * 16 + r * 4, b2);
            accC[0]  = fmaf(v0, w.x, accC[0]);
            accC[1]  = fmaf(v1, w.x, accC[1]);
            accC[2]  = fmaf(v2, w.x, accC[2]);
            accC[3]  = fmaf(v0, w.y, accC[3]);
            accC[4]  = fmaf(v1, w.y, accC[4]);
            accC[5]  = fmaf(v2, w.y, accC[5]);
            accC[6]  = fmaf(v0, w.z, accC[6]);
            accC[7]  = fmaf(v1, w.z, accC[7]);
            accC[8]  = fmaf(v2, w.z, accC[8]);
            accC[9]  = fmaf(v0, w.w, accC[9]);
            accC[10] = fmaf(v1, w.w, accC[10]);
            accC[11] = fmaf(v2, w.w, accC[11]);
        }

        // ---- epilogue: scatter-add by src ----
        int srcn = edge_index[e0 + el];
        float* dstp = g_sums + (size_t)srcn * DIMX;
#pragma unroll
        for (int m = 0; m < 16; ++m)
            atomicAdd(dstp + r * 16 + m, N0C * acc0[m]);

        float s1x = sh1_s[el * 4 + 0], s1y = sh1_s[el * 4 + 1], s1z = sh1_s[el * 4 + 2];
        const float n1i = N1C * I3C;
#pragma unroll
        for (int j = 0; j < 4; ++j) {
            int w = r * 4 + j;
            float bb = accB[j];
            atomicAdd(dstp + M0 + w * 3 + 0, n1i * (bb * s1x + accC[j * 3 + 0] * sh0v));
            atomicAdd(dstp + M0 + w * 3 + 1, n1i * (bb * s1y + accC[j * 3 + 1] * sh0v));
            atomicAdd(dstp + M0 + w * 3 + 2, n1i * (bb * s1z + accC[j * 3 + 2] * sh0v));
        }
    }
}

__global__ void finalize(const float* __restrict__ node_attr, float* __restrict__ out) {
    int i = blockIdx.x * blockDim.x + threadIdx.x;
    if (i >= NN * DIMX) return;
    int n = i / DIMX;
    float c = fmaxf(g_cnt[n], 1.0f);
    out[i] = g_sums[i] / c + node_attr[i];
}

extern "C" void kernel_launch(void* const* d_in, const int* in_sizes, int n_in,
                              void* d_out, int out_size) {
    const float* node_attr  = (const float*)d_in[0];
    const int*   edge_index = (const int*)  d_in[1];
    const float* edge_attr  = (const float*)d_in[2];
    const float* edge_sh    = (const float*)d_in[3];
    const float* W1         = (const float*)d_in[6];
    const float* b1         = (const float*)d_in[7];
    const float* W2         = (const float*)d_in[8];
    const float* b2         = (const float*)d_in[9];
    float* out = (float*)d_out;

    const int smem_bytes = (TM * HS + 8512 + TM + TM * 4) * (int)sizeof(float); // 69120
    cudaFuncSetAttribute(tp_main, cudaFuncAttributeMaxDynamicSharedMemorySize, smem_bytes);

    zero_kernel<<<(NN * DIMX + 255) / 256, 256>>>();
    transpose_w2<<<(WNUM * HIDD + 255) / 256, 256>>>(W2);
    tp_main<<<EE / TM, 256, smem_bytes>>>(node_attr, edge_index, edge_attr,
                                          edge_sh, W1, b1, b2);
    finalize<<<(NN * DIMX + 255) / 256, 256>>>(node_attr, out);
}